// round 11
// baseline (speedup 1.0000x reference)
#include <cuda_runtime.h>
#include <math.h>
#include <stdint.h>

#define N_NODES 100000
#define N_EDGES 1000000
#define DIM     128
#define NH      4
#define NJ      8
#define NK      1000
#define NC      40
#define TOPK    8000            // NJ*NK per head
#define NBINS   65536
#define NCHUNK  256             // 256 chunks x 256 bins
#define CAP     16384
#define NG      32              // NJ*NH
#define NROWS   (NG*NK)         // 32000 msg rows
#define NMASKW  ((N_NODES + 7) / 8)

#define BPSM    6
#define GRID    (148*BPSM)      // 888 blocks, one co-resident wave
#define TPB     256
#define GTH     (GRID*TPB)
#define NLEAF   32
#define MBLK    256             // blocks participating in merged scan phase
#define MLEAF   8

// ---------------- scratch (all self-cleaning or rewritten every run) ----------
__device__ int                 d_deg[N_NODES];         // zeroed in phase 3
__device__ unsigned            d_hist[NH * NBINS];     // zeroed in phase 1
__device__ float               d_acc[N_NODES * NH];    // zeroed in phase 3
__device__ unsigned short      d_locmap[N_NODES * NH]; // cleared in phase 9 via sidx
__device__ unsigned            d_mask[NMASKW];         // 4-bit presence; cleared phase 9
__device__ int                 d_flag[NROWS];          // cleared per-row phase 9
__device__ float               d_pooled[NJ * DIM];     // zeroed in phase 10
__device__ int                 d_nrows;                // reset in phase 10
__device__ int                 d_rowctr;               // reset in phase 10
__device__ float               d_msg[NROWS * DIM];     // cleared per-row phase 9
__device__ float               d_p[N_NODES * NH];      // p, overwritten by q in 2a
__device__ float               d_scores[N_NODES * NH];
__device__ unsigned            d_csum[NH * NCHUNK];
__device__ unsigned            d_pref[NH * NBINS];
__device__ int                 d_B[NH];
__device__ int                 d_cnt[NH];
__device__ unsigned long long  d_cbuf[NH * CAP];
__device__ int                 d_sidx[NH * TOPK];
__device__ float               d_vals[NH * TOPK];
__device__ int                 d_rows[NROWS];

// ---------------- grid barrier: flat arrivals, FANOUT release -----------------
__device__ unsigned g_cnt = 0;
__device__ __align__(128) unsigned g_genw[NLEAF * 32];  // one word per 128B line
__device__ unsigned m_cnt = 0;
__device__ __align__(128) unsigned m_genw[MLEAF * 32];

__device__ __forceinline__ unsigned ld_acq(unsigned* p) {
    unsigned v;
    asm volatile("ld.acquire.gpu.global.u32 %0, [%1];" : "=r"(v) : "l"(p) : "memory");
    return v;
}
__device__ __forceinline__ void st_rel(unsigned* p, unsigned v) {
    asm volatile("st.release.gpu.global.u32 [%0], %1;" :: "l"(p), "r"(v) : "memory");
}

__device__ __forceinline__ void gridbar() {
    __syncthreads();
    if (threadIdx.x == 0) {
        unsigned* myw = &g_genw[(blockIdx.x & (NLEAF - 1)) * 32];
        unsigned gen = ld_acq(myw);
        __threadfence();
        if (atomicAdd(&g_cnt, 1u) == (unsigned)(GRID - 1)) {
            g_cnt = 0;
            #pragma unroll
            for (int l = 0; l < NLEAF; l++)
                st_rel(&g_genw[l * 32], gen + 1u);
        } else {
            unsigned ns = 16;
            while (ld_acq(myw) == gen) {
                __nanosleep(ns);
                if (ns < 256) ns += ns;
            }
        }
    }
    __syncthreads();
}

// mini-barrier among blocks [0, MBLK)
__device__ __forceinline__ void minibar() {
    __syncthreads();
    if (threadIdx.x == 0) {
        unsigned* myw = &m_genw[(blockIdx.x & (MLEAF - 1)) * 32];
        unsigned gen = ld_acq(myw);
        __threadfence();
        if (atomicAdd(&m_cnt, 1u) == (unsigned)(MBLK - 1)) {
            m_cnt = 0;
            #pragma unroll
            for (int l = 0; l < MLEAF; l++)
                st_rel(&m_genw[l * 32], gen + 1u);
        } else {
            unsigned ns = 16;
            while (ld_acq(myw) == gen) {
                __nanosleep(ns);
                if (ns < 256) ns += ns;
            }
        }
    }
    __syncthreads();
}

__device__ __forceinline__ unsigned flip_key(float f) {
    unsigned u = __float_as_uint(f);
    return (u >> 31) ? ~u : (u | 0x80000000u);
}

// ================= THE kernel ================================================
__global__ void __launch_bounds__(TPB, BPSM)
K(const float* __restrict__ x, const float* __restrict__ wr,
  const int* __restrict__ ei, const float* __restrict__ ea,
  const float* __restrict__ W1, const float* __restrict__ W2,
  float* __restrict__ out) {
    __shared__ float sbuf[768];
    __shared__ int   sctl[2];
    const int gtid = blockIdx.x * TPB + threadIdx.x;
    const int t = threadIdx.x;
    const int4* u4p = reinterpret_cast<const int4*>(ei);
    const int4* v4p = reinterpret_cast<const int4*>(ei + N_EDGES);

    // ---- phase 1: zero hist + in-degree RED + p = x @ w_rank ----
    {
        uint4* ph = reinterpret_cast<uint4*>(d_hist);
        for (int i = gtid; i < (NH * NBINS) / 4; i += GTH)
            ph[i] = make_uint4(0, 0, 0, 0);
    }
    for (int i = gtid; i < N_EDGES / 4; i += GTH) {
        int4 v4 = __ldg(v4p + i);
        atomicAdd(&d_deg[v4.x], 1);
        atomicAdd(&d_deg[v4.y], 1);
        atomicAdd(&d_deg[v4.z], 1);
        atomicAdd(&d_deg[v4.w], 1);
    }
    {
        float* ws = sbuf;                          // w_rank: 512 floats
        for (int i = t; i < DIM * NH; i += TPB) ws[i] = __ldg(&wr[i]);
        __syncthreads();
        for (int n = gtid; n < N_NODES; n += GTH) {
            const float4* xr = reinterpret_cast<const float4*>(x + (size_t)n * DIM);
            float a0 = 0, a1 = 0, a2 = 0, a3 = 0;
            #pragma unroll 4
            for (int c4 = 0; c4 < DIM / 4; c4++) {
                float4 xv = __ldg(&xr[c4]);
                int b = c4 * 16;
                a0 += xv.x * ws[b+0] + xv.y * ws[b+4] + xv.z * ws[b+8]  + xv.w * ws[b+12];
                a1 += xv.x * ws[b+1] + xv.y * ws[b+5] + xv.z * ws[b+9]  + xv.w * ws[b+13];
                a2 += xv.x * ws[b+2] + xv.y * ws[b+6] + xv.z * ws[b+10] + xv.w * ws[b+14];
                a3 += xv.x * ws[b+3] + xv.y * ws[b+7] + xv.z * ws[b+11] + xv.w * ws[b+15];
            }
            *reinterpret_cast<float4*>(&d_p[n * NH]) = make_float4(a0, a1, a2, a3);
        }
    }
    gridbar();

    // ---- phase 2a: q = p * rsqrt(deg+1), in place ----
    for (int n = gtid; n < N_NODES; n += GTH) {
        float rs = rsqrtf((float)d_deg[n] + 1.0f);
        float4 p4 = *reinterpret_cast<const float4*>(&d_p[n * NH]);
        *reinterpret_cast<float4*>(&d_p[n * NH]) =
            make_float4(p4.x * rs, p4.y * rs, p4.z * rs, p4.w * rs);
    }
    gridbar();

    // ---- phase 2b: acc[v] += q[u] ----
    for (int i = gtid; i < N_EDGES / 4; i += GTH) {
        int4 u4 = __ldg(u4p + i);
        int4 v4 = __ldg(v4p + i);
        int us[4] = {u4.x, u4.y, u4.z, u4.w};
        int vs[4] = {v4.x, v4.y, v4.z, v4.w};
        float4 qq[4];
        #pragma unroll
        for (int s = 0; s < 4; s++)
            qq[s] = __ldg(reinterpret_cast<const float4*>(&d_p[us[s] * NH]));
        #pragma unroll
        for (int s = 0; s < 4; s++) {
            asm volatile("red.global.add.v4.f32 [%0], {%1, %2, %3, %4};"
                         :: "l"(&d_acc[vs[s] * NH]),
                            "f"(qq[s].x), "f"(qq[s].y), "f"(qq[s].z), "f"(qq[s].w)
                         : "memory");
        }
    }
    gridbar();

    // ---- phase 3: scores = rs*(q+acc); histogram; self-clean deg + acc ----
    for (int n = gtid; n < N_NODES; n += GTH) {
        float rs  = rsqrtf((float)d_deg[n] + 1.0f);
        float4 q4 = *reinterpret_cast<const float4*>(&d_p[n * NH]);
        float4 a4 = *reinterpret_cast<const float4*>(&d_acc[n * NH]);
        float4 s4 = make_float4(rs * (q4.x + a4.x), rs * (q4.y + a4.y),
                                rs * (q4.z + a4.z), rs * (q4.w + a4.w));
        *reinterpret_cast<float4*>(&d_scores[n * NH]) = s4;
        d_deg[n] = 0;                                               // self-clean
        *reinterpret_cast<float4*>(&d_acc[n * NH]) = make_float4(0, 0, 0, 0);
        atomicAdd(&d_hist[0 * NBINS + (flip_key(s4.x) >> 16)], 1u);
        atomicAdd(&d_hist[1 * NBINS + (flip_key(s4.y) >> 16)], 1u);
        atomicAdd(&d_hist[2 * NBINS + (flip_key(s4.z) >> 16)], 1u);
        atomicAdd(&d_hist[3 * NBINS + (flip_key(s4.w) >> 16)], 1u);
    }
    gridbar();

    // ---- phase 45 (blocks 0..MBLK-1): chunk sums; minibar; prefix + threshold ----
    if (blockIdx.x < MBLK) {
        {   // stage A: chunk sums
            unsigned* sh = reinterpret_cast<unsigned*>(sbuf);
            for (int j = blockIdx.x; j < NH * NCHUNK; j += MBLK) {
                int h = j >> 8, c = j & 255;
                sh[t] = d_hist[h * NBINS + (NBINS - 1 - (c * 256 + t))];
                __syncthreads();
                for (int off = 128; off; off >>= 1) {
                    if (t < off) sh[t] += sh[t + off];
                    __syncthreads();
                }
                if (t == 0) d_csum[h * NCHUNK + c] = sh[0];
                __syncthreads();
            }
        }
        minibar();
        {   // stage B: chunk prefix + bin prefix + threshold
            unsigned* sh = reinterpret_cast<unsigned*>(sbuf);
            unsigned* sb = reinterpret_cast<unsigned*>(sbuf) + 256;
            for (int j = blockIdx.x; j < NH * NCHUNK; j += MBLK) {
                int h = j >> 8, c = j & 255;
                sh[t] = d_csum[h * NCHUNK + t];
                __syncthreads();
                for (int off = 1; off < 256; off <<= 1) {
                    unsigned v = (t >= off) ? sh[t - off] : 0u;
                    __syncthreads();
                    sh[t] += v;
                    __syncthreads();
                }
                unsigned base = (c > 0) ? sh[c - 1] : 0u;
                int bin = NBINS - 1 - (c * 256 + t);
                unsigned hv = d_hist[h * NBINS + bin];
                sb[t] = hv;
                __syncthreads();
                for (int off = 1; off < 256; off <<= 1) {
                    unsigned v = (t >= off) ? sb[t - off] : 0u;
                    __syncthreads();
                    sb[t] += v;
                    __syncthreads();
                }
                unsigned excl = base + sb[t] - hv;
                d_pref[h * NBINS + bin] = excl;
                if (excl < TOPK && excl + hv >= TOPK) {
                    d_B[h]   = bin;
                    d_cnt[h] = (int)(excl + hv);
                }
                __syncthreads();
            }
        }
    }
    gridbar();

    // ---- phase 6: counting-sort candidates into bin segments ----
    {
        int Bs[4] = {d_B[0], d_B[1], d_B[2], d_B[3]};
        for (int n = gtid; n < N_NODES; n += GTH) {
            float4 s4 = *reinterpret_cast<const float4*>(&d_scores[n * NH]);
            float sv[4] = {s4.x, s4.y, s4.z, s4.w};
            #pragma unroll
            for (int h = 0; h < NH; h++) {
                unsigned key = flip_key(sv[h]);
                int bin = (int)(key >> 16);
                if (bin >= Bs[h]) {
                    unsigned slot = atomicAdd(&d_pref[h * NBINS + bin], 1u);
                    if (slot < CAP)
                        d_cbuf[h * CAP + slot] =
                            ((unsigned long long)key << 32) | (unsigned)(~(unsigned)n);
                }
            }
        }
    }
    gridbar();

    // ---- phase 7: exact rank; emit sidx/vals/locmap + presence nibble ----
    for (int i = gtid; i < NH * CAP; i += GTH) {
        int h = i / CAP, slot = i % CAP;
        if (slot >= d_cnt[h]) continue;
        unsigned long long key = d_cbuf[h * CAP + slot];
        int bin = (int)(key >> 48);
        unsigned segEnd   = d_pref[h * NBINS + bin];   // post-compact = base+occ
        unsigned occ      = d_hist[h * NBINS + bin];
        unsigned segStart = segEnd - occ;
        int rank = (int)segStart;
        for (unsigned j = segStart; j < segEnd; j++)
            if (d_cbuf[h * CAP + j] > key) rank++;
        if (rank < TOPK) {
            unsigned key32 = (unsigned)(key >> 32);
            int n = (int)(~(unsigned)key);
            float f = __uint_as_float((key32 & 0x80000000u) ? (key32 & 0x7FFFFFFFu)
                                                            : ~key32);
            d_sidx[h * TOPK + rank] = n;
            d_vals[h * TOPK + rank] = f;
            d_locmap[n * NH + h] = (unsigned short)(rank + 1);
            atomicOr(&d_mask[n >> 3], (1u << h) << ((n & 7) * 4));
        }
    }
    gridbar();

    // ---- phase 8: nibble-gated triples + immediate axpy y[row] += w*x[node] ----
    for (int i = gtid; i < N_EDGES / 4; i += GTH) {
        int4 u4 = __ldg(u4p + i);
        int us[4] = {u4.x, u4.y, u4.z, u4.w};
        unsigned mu[4];
        #pragma unroll
        for (int s = 0; s < 4; s++)
            mu[s] = (__ldg(&d_mask[us[s] >> 3]) >> ((us[s] & 7) * 4)) & 0xFu;
        if (!(mu[0] | mu[1] | mu[2] | mu[3])) continue;
        int4 v4 = __ldg(v4p + i);
        int vs[4] = {v4.x, v4.y, v4.z, v4.w};
        #pragma unroll
        for (int s = 0; s < 4; s++) {
            if (!mu[s]) continue;
            unsigned mv = (__ldg(&d_mask[vs[s] >> 3]) >> ((vs[s] & 7) * 4)) & 0xFu;
            unsigned mm = mu[s] & mv;
            if (!mm) continue;                     // survives ~2.5% of edges
            unsigned long long LU =
                __ldg(reinterpret_cast<const unsigned long long*>(&d_locmap[us[s] * NH]));
            unsigned long long LV =
                __ldg(reinterpret_cast<const unsigned long long*>(&d_locmap[vs[s] * NH]));
            #pragma unroll
            for (int h = 0; h < NH; h++) {
                if (!((mm >> h) & 1u)) continue;
                int pu = (int)((LU >> (16 * h)) & 0xFFFFu) - 1;
                int pv = (int)((LV >> (16 * h)) & 0xFFFFu) - 1;
                int jju = pu / NK;
                if (jju != pv / NK) continue;
                float w = __ldg(&ea[4 * i + s]);
                int g   = jju * NH + h;
                int ku  = pu - jju * NK;
                int kv  = pv - jju * NK;
                int row = g * NK + ku;
                int node = d_sidx[h * TOPK + jju * NK + kv];
                if (atomicExch(&d_flag[row], 1) == 0) {
                    int rp = atomicAdd(&d_nrows, 1);
                    d_rows[rp] = row;
                }
                const float4* xr = reinterpret_cast<const float4*>(x + (size_t)node * DIM);
                float* y = &d_msg[(size_t)row * DIM];
                #pragma unroll 4
                for (int c4 = 0; c4 < DIM / 4; c4++) {
                    float4 xv = __ldg(&xr[c4]);
                    asm volatile("red.global.add.v4.f32 [%0], {%1, %2, %3, %4};"
                                 :: "l"(y + c4 * 4),
                                    "f"(w * xv.x), "f"(w * xv.y), "f"(w * xv.z), "f"(w * xv.w)
                                 : "memory");
                }
            }
        }
    }
    gridbar();

    // ---- phase 9: clear locmap+mask; dynamic rows: gemv + pool + self-clean ----
    for (int i = gtid; i < NH * TOPK; i += GTH) {
        int h = i / TOPK;
        int n = d_sidx[i];
        d_locmap[n * NH + h] = 0;
    }
    for (int i = gtid; i < NMASKW; i += GTH) d_mask[i] = 0u;
    {
        float* ys = sbuf;                           // 2 x 128
        int nr = d_nrows;
        int half = t >> 7, tl = t & 127;
        for (;;) {
            __syncthreads();
            if (t == 0) sctl[0] = atomicAdd(&d_rowctr, 2);
            __syncthreads();
            int rb = sctl[0];
            if (rb >= nr) break;
            int r = rb + half;
            bool active = (r < nr);
            int row = 0;
            if (active) {
                row = d_rows[r];
                ys[half * DIM + tl] = d_msg[(size_t)row * DIM + tl];
                d_msg[(size_t)row * DIM + tl] = 0.0f;   // self-clean
                if (tl == 0) d_flag[row] = 0;           // self-clean
            }
            __syncthreads();
            if (active) {
                const float* yrow = &ys[half * DIM];
                float acc = 0.0f;
                #pragma unroll 8
                for (int c = 0; c < DIM; c++) acc += yrow[c] * __ldg(&W1[c * DIM + tl]);
                if (acc > 0.0f) {
                    int g = row / NK, ku = row - g * NK;
                    int h = g & 3, jj = g >> 2;
                    float pv = d_vals[h * TOPK + jj * NK + ku];
                    float sg = 1.0f / (1.0f + __expf(-pv));
                    atomicAdd(&d_pooled[jj * DIM + tl], acc * sg);
                }
            }
        }
    }
    gridbar();

    // ---- phase 10: one block per jj: out row = log_softmax((pooled_jj/4000)@W2) ----
    if (blockIdx.x < NJ) {
        int jj = blockIdx.x;
        float* lg   = sbuf;          // 40
        float* mxse = sbuf + 48;     // 2
        if (t < NC) {
            float sacc = 0.0f;
            for (int d = 0; d < DIM; d++)
                sacc += d_pooled[jj * DIM + d] * __ldg(&W2[d * NC + t]);
            lg[t] = sacc * (1.0f / 4000.0f);
        }
        __syncthreads();
        if (t < DIM) d_pooled[jj * DIM + t] = 0.0f;          // self-clean
        if (blockIdx.x == 0 && t == 0) { d_nrows = 0; d_rowctr = 0; }
        if (t == 0) {
            float mx = -1e30f;
            for (int c = 0; c < NC; c++) mx = fmaxf(mx, lg[c]);
            float se = 0.0f;
            for (int c = 0; c < NC; c++) se += __expf(lg[c] - mx);
            mxse[0] = mx;
            mxse[1] = __logf(se);
        }
        __syncthreads();
        if (t < NC) out[jj * NC + t] = lg[t] - mxse[0] - mxse[1];
    }
}

// ---------------- host launcher: ONE node ----------------
extern "C" void kernel_launch(void* const* d_in, const int* in_sizes, int n_in,
                              void* d_out, int out_size) {
    const float* x         = (const float*)d_in[0];
    const float* edge_attr = (const float*)d_in[1];
    const float* w_rank    = (const float*)d_in[2];
    const float* W1        = (const float*)d_in[3];
    const float* W2        = (const float*)d_in[4];
    const int*   ei        = (const int*)d_in[5];
    float*       out       = (float*)d_out;

    K<<<GRID, TPB>>>(x, w_rank, ei, edge_attr, W1, W2, out);
}

// round 12
// speedup vs baseline: 1.9489x; 1.9489x over previous
#include <cuda_runtime.h>
#include <math.h>
#include <stdint.h>

#define N_NODES 100000
#define N_EDGES 1000000
#define DIM     128
#define NH      4
#define NJ      8
#define NK      1000
#define NC      40
#define TOPK    8000            // NJ*NK per head
#define NBINS   65536
#define NCHUNK  256             // 256 chunks x 256 bins
#define CAP     16384
#define NG      32              // NJ*NH
#define NROWS   (NG*NK)         // 32000 msg rows
#define NMASKW  ((N_NODES + 7) / 8)
#define NQUAD   (N_EDGES / 4)

// ---------------- scratch (all self-cleaning or rewritten every run) ----------
__device__ int                 d_deg[N_NODES];         // zeroed in K3
__device__ unsigned            d_hist[NH * NBINS];     // zeroed in K1
__device__ float               d_acc[N_NODES * NH];    // zeroed in K3
__device__ unsigned short      d_locmap[N_NODES * NH]; // cleared in K9 via sidx
__device__ unsigned            d_mask[NMASKW];         // 4-bit presence; cleared K9
__device__ int                 d_flag[NROWS];          // cleared per-row K9
__device__ float               d_pooled[NJ * DIM];     // zeroed in K10
__device__ int                 d_nrows;                // reset in K10
__device__ int                 d_rowctr;               // reset in K10
__device__ float               d_msg[NROWS * DIM];     // cleared per-row K9
__device__ float               d_p[N_NODES * NH];      // p, overwritten by q
__device__ float               d_scores[N_NODES * NH];
__device__ unsigned            d_csum[NH * NCHUNK];
__device__ unsigned            d_pref[NH * NBINS];
__device__ int                 d_B[NH];
__device__ int                 d_cnt[NH];
__device__ unsigned long long  d_cbuf[NH * CAP];
__device__ int                 d_sidx[NH * TOPK];
__device__ float               d_vals[NH * TOPK];
__device__ int                 d_rows[NROWS];

__device__ __forceinline__ unsigned flip_key(float f) {
    unsigned u = __float_as_uint(f);
    return (u >> 31) ? ~u : (u | 0x80000000u);
}

// ---- K1: zero hist + in-degree RED + p = x @ w_rank --------------------------
__global__ void K1(const float* __restrict__ x, const float* __restrict__ wr,
                   const int* __restrict__ ei) {
    __shared__ float ws[DIM * NH];
    const int GTH = gridDim.x * blockDim.x;
    const int gtid = blockIdx.x * blockDim.x + threadIdx.x;
    const int t = threadIdx.x;
    const int4* v4p = reinterpret_cast<const int4*>(ei + N_EDGES);

    {
        uint4* ph = reinterpret_cast<uint4*>(d_hist);
        for (int i = gtid; i < (NH * NBINS) / 4; i += GTH)
            ph[i] = make_uint4(0, 0, 0, 0);
    }
    for (int i = gtid; i < NQUAD; i += GTH) {
        int4 v4 = __ldg(v4p + i);
        atomicAdd(&d_deg[v4.x], 1);
        atomicAdd(&d_deg[v4.y], 1);
        atomicAdd(&d_deg[v4.z], 1);
        atomicAdd(&d_deg[v4.w], 1);
    }
    for (int i = t; i < DIM * NH; i += blockDim.x) ws[i] = __ldg(&wr[i]);
    __syncthreads();
    for (int n = gtid; n < N_NODES; n += GTH) {
        const float4* xr = reinterpret_cast<const float4*>(x + (size_t)n * DIM);
        float a0 = 0, a1 = 0, a2 = 0, a3 = 0;
        #pragma unroll 4
        for (int c4 = 0; c4 < DIM / 4; c4++) {
            float4 xv = __ldg(&xr[c4]);
            int b = c4 * 16;
            a0 += xv.x * ws[b+0] + xv.y * ws[b+4] + xv.z * ws[b+8]  + xv.w * ws[b+12];
            a1 += xv.x * ws[b+1] + xv.y * ws[b+5] + xv.z * ws[b+9]  + xv.w * ws[b+13];
            a2 += xv.x * ws[b+2] + xv.y * ws[b+6] + xv.z * ws[b+10] + xv.w * ws[b+14];
            a3 += xv.x * ws[b+3] + xv.y * ws[b+7] + xv.z * ws[b+11] + xv.w * ws[b+15];
        }
        *reinterpret_cast<float4*>(&d_p[n * NH]) = make_float4(a0, a1, a2, a3);
    }
}

// ---- K2a: q = p * rsqrt(deg+1), in place --------------------------------------
__global__ void K2a() {
    int n = blockIdx.x * blockDim.x + threadIdx.x;
    if (n >= N_NODES) return;
    float rs = rsqrtf((float)d_deg[n] + 1.0f);
    float4 p4 = *reinterpret_cast<const float4*>(&d_p[n * NH]);
    *reinterpret_cast<float4*>(&d_p[n * NH]) =
        make_float4(p4.x * rs, p4.y * rs, p4.z * rs, p4.w * rs);
}

// ---- K2b: acc[v] += q[u] ------------------------------------------------------
__global__ void K2b(const int* __restrict__ ei) {
    int i = blockIdx.x * blockDim.x + threadIdx.x;
    if (i >= NQUAD) return;
    const int4* u4p = reinterpret_cast<const int4*>(ei);
    const int4* v4p = reinterpret_cast<const int4*>(ei + N_EDGES);
    int4 u4 = __ldg(u4p + i);
    int4 v4 = __ldg(v4p + i);
    int us[4] = {u4.x, u4.y, u4.z, u4.w};
    int vs[4] = {v4.x, v4.y, v4.z, v4.w};
    float4 qq[4];
    #pragma unroll
    for (int s = 0; s < 4; s++)
        qq[s] = __ldg(reinterpret_cast<const float4*>(&d_p[us[s] * NH]));
    #pragma unroll
    for (int s = 0; s < 4; s++) {
        asm volatile("red.global.add.v4.f32 [%0], {%1, %2, %3, %4};"
                     :: "l"(&d_acc[vs[s] * NH]),
                        "f"(qq[s].x), "f"(qq[s].y), "f"(qq[s].z), "f"(qq[s].w)
                     : "memory");
    }
}

// ---- K3: scores = rs*(q+acc); histogram; self-clean deg + acc -----------------
__global__ void K3() {
    int n = blockIdx.x * blockDim.x + threadIdx.x;
    if (n >= N_NODES) return;
    float rs  = rsqrtf((float)d_deg[n] + 1.0f);
    float4 q4 = *reinterpret_cast<const float4*>(&d_p[n * NH]);
    float4 a4 = *reinterpret_cast<const float4*>(&d_acc[n * NH]);
    float4 s4 = make_float4(rs * (q4.x + a4.x), rs * (q4.y + a4.y),
                            rs * (q4.z + a4.z), rs * (q4.w + a4.w));
    *reinterpret_cast<float4*>(&d_scores[n * NH]) = s4;
    d_deg[n] = 0;                                               // self-clean
    *reinterpret_cast<float4*>(&d_acc[n * NH]) = make_float4(0, 0, 0, 0);
    atomicAdd(&d_hist[0 * NBINS + (flip_key(s4.x) >> 16)], 1u);
    atomicAdd(&d_hist[1 * NBINS + (flip_key(s4.y) >> 16)], 1u);
    atomicAdd(&d_hist[2 * NBINS + (flip_key(s4.z) >> 16)], 1u);
    atomicAdd(&d_hist[3 * NBINS + (flip_key(s4.w) >> 16)], 1u);
}

// ---- K4: chunk sums (one job per block) ---------------------------------------
__global__ void K4() {
    __shared__ unsigned sh[256];
    int t = threadIdx.x;
    int h = blockIdx.x >> 8, c = blockIdx.x & 255;
    sh[t] = d_hist[h * NBINS + (NBINS - 1 - (c * 256 + t))];
    __syncthreads();
    for (int off = 128; off; off >>= 1) {
        if (t < off) sh[t] += sh[t + off];
        __syncthreads();
    }
    if (t == 0) d_csum[h * NCHUNK + c] = sh[0];
}

// ---- K5: chunk prefix + bin prefix + threshold (one job per block) ------------
__global__ void K5() {
    __shared__ unsigned sh[256];
    __shared__ unsigned sb[256];
    int t = threadIdx.x;
    int h = blockIdx.x >> 8, c = blockIdx.x & 255;
    sh[t] = d_csum[h * NCHUNK + t];
    __syncthreads();
    for (int off = 1; off < 256; off <<= 1) {
        unsigned v = (t >= off) ? sh[t - off] : 0u;
        __syncthreads();
        sh[t] += v;
        __syncthreads();
    }
    unsigned base = (c > 0) ? sh[c - 1] : 0u;
    int bin = NBINS - 1 - (c * 256 + t);
    unsigned hv = d_hist[h * NBINS + bin];
    sb[t] = hv;
    __syncthreads();
    for (int off = 1; off < 256; off <<= 1) {
        unsigned v = (t >= off) ? sb[t - off] : 0u;
        __syncthreads();
        sb[t] += v;
        __syncthreads();
    }
    unsigned excl = base + sb[t] - hv;
    d_pref[h * NBINS + bin] = excl;
    if (excl < TOPK && excl + hv >= TOPK) {
        d_B[h]   = bin;
        d_cnt[h] = (int)(excl + hv);
    }
}

// ---- K6: counting-sort candidates into bin segments ---------------------------
__global__ void K6() {
    int n = blockIdx.x * blockDim.x + threadIdx.x;
    if (n >= N_NODES) return;
    float4 s4 = *reinterpret_cast<const float4*>(&d_scores[n * NH]);
    float sv[4] = {s4.x, s4.y, s4.z, s4.w};
    #pragma unroll
    for (int h = 0; h < NH; h++) {
        unsigned key = flip_key(sv[h]);
        int bin = (int)(key >> 16);
        if (bin >= d_B[h]) {
            unsigned slot = atomicAdd(&d_pref[h * NBINS + bin], 1u);
            if (slot < CAP)
                d_cbuf[h * CAP + slot] =
                    ((unsigned long long)key << 32) | (unsigned)(~(unsigned)n);
        }
    }
}

// ---- K7: exact rank; emit sidx/vals/locmap + presence nibble ------------------
__global__ void K7() {
    int i = blockIdx.x * blockDim.x + threadIdx.x;
    int h = i / CAP, slot = i % CAP;
    if (slot >= d_cnt[h]) return;
    unsigned long long key = d_cbuf[h * CAP + slot];
    int bin = (int)(key >> 48);
    unsigned segEnd   = d_pref[h * NBINS + bin];   // post-compact = base+occ
    unsigned occ      = d_hist[h * NBINS + bin];
    unsigned segStart = segEnd - occ;
    int rank = (int)segStart;
    for (unsigned j = segStart; j < segEnd; j++)
        if (d_cbuf[h * CAP + j] > key) rank++;
    if (rank < TOPK) {
        unsigned key32 = (unsigned)(key >> 32);
        int n = (int)(~(unsigned)key);
        float f = __uint_as_float((key32 & 0x80000000u) ? (key32 & 0x7FFFFFFFu)
                                                        : ~key32);
        d_sidx[h * TOPK + rank] = n;
        d_vals[h * TOPK + rank] = f;
        d_locmap[n * NH + h] = (unsigned short)(rank + 1);
        atomicOr(&d_mask[n >> 3], (1u << h) << ((n & 7) * 4));
    }
}

// ---- K8: nibble-gated triples + immediate axpy y[row] += w*x[node] ------------
__global__ void K8(const int* __restrict__ ei, const float* __restrict__ ea,
                   const float* __restrict__ x) {
    int i = blockIdx.x * blockDim.x + threadIdx.x;
    if (i >= NQUAD) return;
    const int4* u4p = reinterpret_cast<const int4*>(ei);
    const int4* v4p = reinterpret_cast<const int4*>(ei + N_EDGES);
    int4 u4 = __ldg(u4p + i);
    int us[4] = {u4.x, u4.y, u4.z, u4.w};
    unsigned mu[4];
    #pragma unroll
    for (int s = 0; s < 4; s++)
        mu[s] = (__ldg(&d_mask[us[s] >> 3]) >> ((us[s] & 7) * 4)) & 0xFu;
    if (!(mu[0] | mu[1] | mu[2] | mu[3])) return;
    int4 v4 = __ldg(v4p + i);
    int vs[4] = {v4.x, v4.y, v4.z, v4.w};
    #pragma unroll
    for (int s = 0; s < 4; s++) {
        if (!mu[s]) continue;
        unsigned mv = (__ldg(&d_mask[vs[s] >> 3]) >> ((vs[s] & 7) * 4)) & 0xFu;
        unsigned mm = mu[s] & mv;
        if (!mm) continue;                     // survives ~2.5% of edges
        unsigned long long LU =
            __ldg(reinterpret_cast<const unsigned long long*>(&d_locmap[us[s] * NH]));
        unsigned long long LV =
            __ldg(reinterpret_cast<const unsigned long long*>(&d_locmap[vs[s] * NH]));
        #pragma unroll
        for (int h = 0; h < NH; h++) {
            if (!((mm >> h) & 1u)) continue;
            int pu = (int)((LU >> (16 * h)) & 0xFFFFu) - 1;
            int pv = (int)((LV >> (16 * h)) & 0xFFFFu) - 1;
            int jju = pu / NK;
            if (jju != pv / NK) continue;
            float w = __ldg(&ea[4 * i + s]);
            int g   = jju * NH + h;
            int ku  = pu - jju * NK;
            int kv  = pv - jju * NK;
            int row = g * NK + ku;
            int node = d_sidx[h * TOPK + jju * NK + kv];
            if (atomicExch(&d_flag[row], 1) == 0) {
                int rp = atomicAdd(&d_nrows, 1);
                d_rows[rp] = row;
            }
            const float4* xr = reinterpret_cast<const float4*>(x + (size_t)node * DIM);
            float* y = &d_msg[(size_t)row * DIM];
            #pragma unroll 4
            for (int c4 = 0; c4 < DIM / 4; c4++) {
                float4 xv = __ldg(&xr[c4]);
                asm volatile("red.global.add.v4.f32 [%0], {%1, %2, %3, %4};"
                             :: "l"(y + c4 * 4),
                                "f"(w * xv.x), "f"(w * xv.y), "f"(w * xv.z), "f"(w * xv.w)
                             : "memory");
            }
        }
    }
}

// ---- K9: clear locmap+mask; dynamic rows: gemv + pool + self-clean ------------
__global__ void K9(const float* __restrict__ W1) {
    __shared__ float ys[2 * DIM];
    __shared__ int   sctl[1];
    const int GTH = gridDim.x * blockDim.x;
    const int gtid = blockIdx.x * blockDim.x + threadIdx.x;
    const int t = threadIdx.x;
    for (int i = gtid; i < NH * TOPK; i += GTH) {
        int h = i / TOPK;
        int n = d_sidx[i];
        d_locmap[n * NH + h] = 0;
    }
    for (int i = gtid; i < NMASKW; i += GTH) d_mask[i] = 0u;
    int nr = d_nrows;
    int half = t >> 7, tl = t & 127;
    for (;;) {
        __syncthreads();
        if (t == 0) sctl[0] = atomicAdd(&d_rowctr, 2);
        __syncthreads();
        int rb = sctl[0];
        if (rb >= nr) break;
        int r = rb + half;
        bool active = (r < nr);
        int row = 0;
        if (active) {
            row = d_rows[r];
            ys[half * DIM + tl] = d_msg[(size_t)row * DIM + tl];
            d_msg[(size_t)row * DIM + tl] = 0.0f;   // self-clean
            if (tl == 0) d_flag[row] = 0;           // self-clean
        }
        __syncthreads();
        if (active) {
            const float* yrow = &ys[half * DIM];
            float acc = 0.0f;
            #pragma unroll 8
            for (int c = 0; c < DIM; c++) acc += yrow[c] * __ldg(&W1[c * DIM + tl]);
            if (acc > 0.0f) {
                int g = row / NK, ku = row - g * NK;
                int h = g & 3, jj = g >> 2;
                float pv = d_vals[h * TOPK + jj * NK + ku];
                float sg = 1.0f / (1.0f + __expf(-pv));
                atomicAdd(&d_pooled[jj * DIM + tl], acc * sg);
            }
        }
    }
}

// ---- K10: one block per jj: out row = log_softmax((pooled_jj/4000)@W2) --------
__global__ void K10(const float* __restrict__ W2, float* __restrict__ out) {
    __shared__ float lg[NC];
    __shared__ float mxse[2];
    int jj = blockIdx.x, t = threadIdx.x;
    if (t < NC) {
        float sacc = 0.0f;
        for (int d = 0; d < DIM; d++)
            sacc += d_pooled[jj * DIM + d] * __ldg(&W2[d * NC + t]);
        lg[t] = sacc * (1.0f / 4000.0f);
    }
    __syncthreads();
    d_pooled[jj * DIM + t] = 0.0f;                   // self-clean (t < 128)
    if (jj == 0 && t == 0) { d_nrows = 0; d_rowctr = 0; }
    if (t == 0) {
        float mx = -1e30f;
        for (int c = 0; c < NC; c++) mx = fmaxf(mx, lg[c]);
        float se = 0.0f;
        for (int c = 0; c < NC; c++) se += __expf(lg[c] - mx);
        mxse[0] = mx;
        mxse[1] = __logf(se);
    }
    __syncthreads();
    if (t < NC) out[jj * NC + t] = lg[t] - mxse[0] - mxse[1];
}

// ---------------- host launcher ----------------
extern "C" void kernel_launch(void* const* d_in, const int* in_sizes, int n_in,
                              void* d_out, int out_size) {
    const float* x         = (const float*)d_in[0];
    const float* edge_attr = (const float*)d_in[1];
    const float* w_rank    = (const float*)d_in[2];
    const float* W1        = (const float*)d_in[3];
    const float* W2        = (const float*)d_in[4];
    const int*   ei        = (const int*)d_in[5];
    float*       out       = (float*)d_out;

    const int TB  = 256;
    const int gN  = (N_NODES + TB - 1) / TB;   // 391
    const int gQ  = (NQUAD + TB - 1) / TB;     // 977

    K1 <<<888, TB>>>(x, w_rank, ei);
    K2a<<<gN, TB>>>();
    K2b<<<gQ, TB>>>(ei);
    K3 <<<gN, TB>>>();
    K4 <<<NH * NCHUNK, TB>>>();
    K5 <<<NH * NCHUNK, TB>>>();
    K6 <<<gN, TB>>>();
    K7 <<<(NH * CAP) / TB, TB>>>();
    K8 <<<gQ, TB>>>(ei, edge_attr, x);
    K9 <<<888, TB>>>(W1);
    K10<<<NJ, DIM>>>(W2, out);
}

// round 15
// speedup vs baseline: 2.0724x; 1.0633x over previous
#include <cuda_runtime.h>
#include <math.h>
#include <stdint.h>

#define N_NODES 100000
#define N_EDGES 1000000
#define DIM     128
#define NH      4
#define NJ      8
#define NK      1000
#define NC      40
#define TOPK    8000            // NJ*NK per head
#define NBINS   65536
#define NCHUNK  256             // 256 chunks x 256 bins
#define CAP     16384
#define NG      32              // NJ*NH
#define NROWS   (NG*NK)         // 32000 msg rows
#define NMASKW  ((N_NODES + 7) / 8)
#define NQUAD   (N_EDGES / 4)
#define NQHALF  (NQUAD / 2)

// ---------------- scratch (all self-cleaning or rewritten every run) ----------
__device__ int                 d_deg[N_NODES];         // zeroed in K3
__device__ unsigned            d_hist[NH * NBINS];     // zeroed in K1
__device__ float               d_acc[N_NODES * NH];    // zeroed in K3
__device__ unsigned short      d_locmap[N_NODES * NH]; // cleared in K9 via sidx
__device__ unsigned            d_mask[NMASKW];         // 4-bit presence; cleared K9
__device__ int                 d_flag[NROWS];          // cleared per-row K9
__device__ float               d_pooled[NJ * DIM];     // zeroed in K10
__device__ int                 d_nrows;                // reset in K10
__device__ int                 d_rowctr;               // reset in K10
__device__ float               d_msg[NROWS * DIM];     // cleared per-row K9
__device__ float               d_p[N_NODES * NH];      // p, overwritten by q
__device__ unsigned            d_keys[N_NODES * NH];   // flipped score keys
__device__ unsigned            d_csum[NH * NCHUNK];
__device__ unsigned            d_pref[NH * NBINS];
__device__ int                 d_B[NH];
__device__ int                 d_cnt[NH];
__device__ unsigned long long  d_cbuf[NH * CAP];
__device__ int                 d_sidx[NH * TOPK];
__device__ float               d_vals[NH * TOPK];
__device__ int                 d_rows[NROWS];

__device__ __forceinline__ unsigned flip_key(float f) {
    unsigned u = __float_as_uint(f);
    return (u >> 31) ? ~u : (u | 0x80000000u);
}

// ---- K1: zero hist + in-degree RED + p = x @ w_rank (warp-per-node GEMV) ----
__global__ void K1(const float* __restrict__ x, const float* __restrict__ wr,
                   const int* __restrict__ ei) {
    const int GTH = gridDim.x * blockDim.x;
    const int gtid = blockIdx.x * blockDim.x + threadIdx.x;
    const int4* v4p = reinterpret_cast<const int4*>(ei + N_EDGES);

    {
        uint4* ph = reinterpret_cast<uint4*>(d_hist);
        for (int i = gtid; i < (NH * NBINS) / 4; i += GTH)
            ph[i] = make_uint4(0, 0, 0, 0);
    }
    for (int i = gtid; i < NQUAD; i += GTH) {
        int4 v4 = __ldg(v4p + i);
        atomicAdd(&d_deg[v4.x], 1);
        atomicAdd(&d_deg[v4.y], 1);
        atomicAdd(&d_deg[v4.z], 1);
        atomicAdd(&d_deg[v4.w], 1);
    }
    // GEMV: warp per node, lane covers columns 4*lane..4*lane+3
    const int lane   = threadIdx.x & 31;
    const int warp   = gtid >> 5;
    const int nwarps = GTH >> 5;
    const float4* w4p = reinterpret_cast<const float4*>(wr);
    float4 w0 = __ldg(w4p + lane * 4 + 0);   // wr[4*lane+0][0..3]
    float4 w1 = __ldg(w4p + lane * 4 + 1);
    float4 w2 = __ldg(w4p + lane * 4 + 2);
    float4 w3 = __ldg(w4p + lane * 4 + 3);
    const float4* x4p = reinterpret_cast<const float4*>(x);
    for (int n = warp; n < N_NODES; n += 2 * nwarps) {
        int n2 = n + nwarps;
        bool has2 = (n2 < N_NODES);
        float4 xa = __ldg(x4p + (size_t)n * 32 + lane);
        float4 xb = has2 ? __ldg(x4p + (size_t)n2 * 32 + lane)
                         : make_float4(0, 0, 0, 0);
        float a0 = xa.x * w0.x + xa.y * w1.x + xa.z * w2.x + xa.w * w3.x;
        float a1 = xa.x * w0.y + xa.y * w1.y + xa.z * w2.y + xa.w * w3.y;
        float a2 = xa.x * w0.z + xa.y * w1.z + xa.z * w2.z + xa.w * w3.z;
        float a3 = xa.x * w0.w + xa.y * w1.w + xa.z * w2.w + xa.w * w3.w;
        float b0 = xb.x * w0.x + xb.y * w1.x + xb.z * w2.x + xb.w * w3.x;
        float b1 = xb.x * w0.y + xb.y * w1.y + xb.z * w2.y + xb.w * w3.y;
        float b2 = xb.x * w0.z + xb.y * w1.z + xb.z * w2.z + xb.w * w3.z;
        float b3 = xb.x * w0.w + xb.y * w1.w + xb.z * w2.w + xb.w * w3.w;
        #pragma unroll
        for (int o = 16; o; o >>= 1) {
            a0 += __shfl_xor_sync(0xFFFFFFFFu, a0, o);
            a1 += __shfl_xor_sync(0xFFFFFFFFu, a1, o);
            a2 += __shfl_xor_sync(0xFFFFFFFFu, a2, o);
            a3 += __shfl_xor_sync(0xFFFFFFFFu, a3, o);
            b0 += __shfl_xor_sync(0xFFFFFFFFu, b0, o);
            b1 += __shfl_xor_sync(0xFFFFFFFFu, b1, o);
            b2 += __shfl_xor_sync(0xFFFFFFFFu, b2, o);
            b3 += __shfl_xor_sync(0xFFFFFFFFu, b3, o);
        }
        if (lane == 0) {
            *reinterpret_cast<float4*>(&d_p[n * NH]) = make_float4(a0, a1, a2, a3);
            if (has2)
                *reinterpret_cast<float4*>(&d_p[n2 * NH]) = make_float4(b0, b1, b2, b3);
        }
    }
}

// ---- K2a: q = p * rsqrt(deg+1), in place --------------------------------------
__global__ void K2a() {
    int n = blockIdx.x * blockDim.x + threadIdx.x;
    if (n >= N_NODES) return;
    float rs = rsqrtf((float)d_deg[n] + 1.0f);
    float4 p4 = *reinterpret_cast<const float4*>(&d_p[n * NH]);
    *reinterpret_cast<float4*>(&d_p[n * NH]) =
        make_float4(p4.x * rs, p4.y * rs, p4.z * rs, p4.w * rs);
}

// ---- K2b: acc[v] += q[u]  (2 coalesced quad-streams per thread) ---------------
__global__ void K2b(const int* __restrict__ ei) {
    int i = blockIdx.x * blockDim.x + threadIdx.x;
    if (i >= NQHALF) return;
    const int4* u4p = reinterpret_cast<const int4*>(ei);
    const int4* v4p = reinterpret_cast<const int4*>(ei + N_EDGES);
    int4 ua = __ldg(u4p + i);
    int4 ub = __ldg(u4p + i + NQHALF);
    int4 va = __ldg(v4p + i);
    int4 vb = __ldg(v4p + i + NQHALF);
    int us[8] = {ua.x, ua.y, ua.z, ua.w, ub.x, ub.y, ub.z, ub.w};
    int vs[8] = {va.x, va.y, va.z, va.w, vb.x, vb.y, vb.z, vb.w};
    float4 qq[8];
    #pragma unroll
    for (int s = 0; s < 8; s++)
        qq[s] = __ldg(reinterpret_cast<const float4*>(&d_p[us[s] * NH]));
    #pragma unroll
    for (int s = 0; s < 8; s++) {
        asm volatile("red.global.add.v4.f32 [%0], {%1, %2, %3, %4};"
                     :: "l"(&d_acc[vs[s] * NH]),
                        "f"(qq[s].x), "f"(qq[s].y), "f"(qq[s].z), "f"(qq[s].w)
                     : "memory");
    }
}

// ---- K3: keys = flip(rs*(q+acc)); histogram; self-clean deg + acc -------------
__global__ void K3() {
    int n = blockIdx.x * blockDim.x + threadIdx.x;
    if (n >= N_NODES) return;
    float rs  = rsqrtf((float)d_deg[n] + 1.0f);
    float4 q4 = *reinterpret_cast<const float4*>(&d_p[n * NH]);
    float4 a4 = *reinterpret_cast<const float4*>(&d_acc[n * NH]);
    uint4 k4 = make_uint4(flip_key(rs * (q4.x + a4.x)),
                          flip_key(rs * (q4.y + a4.y)),
                          flip_key(rs * (q4.z + a4.z)),
                          flip_key(rs * (q4.w + a4.w)));
    *reinterpret_cast<uint4*>(&d_keys[n * NH]) = k4;
    d_deg[n] = 0;                                               // self-clean
    *reinterpret_cast<float4*>(&d_acc[n * NH]) = make_float4(0, 0, 0, 0);
    atomicAdd(&d_hist[0 * NBINS + (k4.x >> 16)], 1u);
    atomicAdd(&d_hist[1 * NBINS + (k4.y >> 16)], 1u);
    atomicAdd(&d_hist[2 * NBINS + (k4.z >> 16)], 1u);
    atomicAdd(&d_hist[3 * NBINS + (k4.w >> 16)], 1u);
}

// ---- K4: chunk sums (one job per block) ---------------------------------------
__global__ void K4() {
    __shared__ unsigned sh[256];
    int t = threadIdx.x;
    int h = blockIdx.x >> 8, c = blockIdx.x & 255;
    sh[t] = d_hist[h * NBINS + (NBINS - 1 - (c * 256 + t))];
    __syncthreads();
    for (int off = 128; off; off >>= 1) {
        if (t < off) sh[t] += sh[t + off];
        __syncthreads();
    }
    if (t == 0) d_csum[h * NCHUNK + c] = sh[0];
}

// ---- K5: chunk prefix + bin prefix + threshold (one job per block) ------------
__global__ void K5() {
    __shared__ unsigned sh[256];
    __shared__ unsigned sb[256];
    int t = threadIdx.x;
    int h = blockIdx.x >> 8, c = blockIdx.x & 255;
    sh[t] = d_csum[h * NCHUNK + t];
    __syncthreads();
    for (int off = 1; off < 256; off <<= 1) {
        unsigned v = (t >= off) ? sh[t - off] : 0u;
        __syncthreads();
        sh[t] += v;
        __syncthreads();
    }
    unsigned base = (c > 0) ? sh[c - 1] : 0u;
    int bin = NBINS - 1 - (c * 256 + t);
    unsigned hv = d_hist[h * NBINS + bin];
    sb[t] = hv;
    __syncthreads();
    for (int off = 1; off < 256; off <<= 1) {
        unsigned v = (t >= off) ? sb[t - off] : 0u;
        __syncthreads();
        sb[t] += v;
        __syncthreads();
    }
    unsigned excl = base + sb[t] - hv;
    d_pref[h * NBINS + bin] = excl;
    if (excl < TOPK && excl + hv >= TOPK) {
        d_B[h]   = bin;
        d_cnt[h] = (int)(excl + hv);
    }
}

// ---- K6: counting-sort candidates into bin segments (keys path) ---------------
__global__ void K6() {
    int n = blockIdx.x * blockDim.x + threadIdx.x;
    if (n >= N_NODES) return;
    uint4 k4 = *reinterpret_cast<const uint4*>(&d_keys[n * NH]);
    unsigned kv[4] = {k4.x, k4.y, k4.z, k4.w};
    #pragma unroll
    for (int h = 0; h < NH; h++) {
        unsigned key = kv[h];
        int bin = (int)(key >> 16);
        if (bin >= d_B[h]) {
            unsigned slot = atomicAdd(&d_pref[h * NBINS + bin], 1u);
            if (slot < CAP)
                d_cbuf[h * CAP + slot] =
                    ((unsigned long long)key << 32) | (unsigned)(~(unsigned)n);
        }
    }
}

// ---- K7: exact rank; emit sidx/vals/locmap + presence nibble ------------------
__global__ void K7() {
    int i = blockIdx.x * blockDim.x + threadIdx.x;
    int h = i / CAP, slot = i % CAP;
    if (slot >= d_cnt[h]) return;
    unsigned long long key = d_cbuf[h * CAP + slot];
    int bin = (int)(key >> 48);
    unsigned segEnd   = d_pref[h * NBINS + bin];   // post-compact = base+occ
    unsigned occ      = d_hist[h * NBINS + bin];
    unsigned segStart = segEnd - occ;
    int rank = (int)segStart;
    for (unsigned j = segStart; j < segEnd; j++)
        if (d_cbuf[h * CAP + j] > key) rank++;
    if (rank < TOPK) {
        unsigned key32 = (unsigned)(key >> 32);
        int n = (int)(~(unsigned)key);
        float f = __uint_as_float((key32 & 0x80000000u) ? (key32 & 0x7FFFFFFFu)
                                                        : ~key32);
        d_sidx[h * TOPK + rank] = n;
        d_vals[h * TOPK + rank] = f;
        d_locmap[n * NH + h] = (unsigned short)(rank + 1);
        atomicOr(&d_mask[n >> 3], (1u << h) << ((n & 7) * 4));
    }
}

// ---- K8: nibble-gated triples + immediate axpy y[row] += w*x[node] ------------
__global__ void K8(const int* __restrict__ ei, const float* __restrict__ ea,
                   const float* __restrict__ x) {
    int i = blockIdx.x * blockDim.x + threadIdx.x;
    if (i >= NQUAD) return;
    const int4* u4p = reinterpret_cast<const int4*>(ei);
    const int4* v4p = reinterpret_cast<const int4*>(ei + N_EDGES);
    int4 u4 = __ldg(u4p + i);
    int us[4] = {u4.x, u4.y, u4.z, u4.w};
    unsigned mu[4];
    #pragma unroll
    for (int s = 0; s < 4; s++)
        mu[s] = (__ldg(&d_mask[us[s] >> 3]) >> ((us[s] & 7) * 4)) & 0xFu;
    if (!(mu[0] | mu[1] | mu[2] | mu[3])) return;
    int4 v4 = __ldg(v4p + i);
    int vs[4] = {v4.x, v4.y, v4.z, v4.w};
    #pragma unroll
    for (int s = 0; s < 4; s++) {
        if (!mu[s]) continue;
        unsigned mv = (__ldg(&d_mask[vs[s] >> 3]) >> ((vs[s] & 7) * 4)) & 0xFu;
        unsigned mm = mu[s] & mv;
        if (!mm) continue;                     // survives ~2.5% of edges
        unsigned long long LU =
            __ldg(reinterpret_cast<const unsigned long long*>(&d_locmap[us[s] * NH]));
        unsigned long long LV =
            __ldg(reinterpret_cast<const unsigned long long*>(&d_locmap[vs[s] * NH]));
        #pragma unroll
        for (int h = 0; h < NH; h++) {
            if (!((mm >> h) & 1u)) continue;
            int pu = (int)((LU >> (16 * h)) & 0xFFFFu) - 1;
            int pv = (int)((LV >> (16 * h)) & 0xFFFFu) - 1;
            int jju = pu / NK;
            if (jju != pv / NK) continue;
            float w = __ldg(&ea[4 * i + s]);
            int g   = jju * NH + h;
            int ku  = pu - jju * NK;
            int kv  = pv - jju * NK;
            int row = g * NK + ku;
            int node = d_sidx[h * TOPK + jju * NK + kv];
            if (atomicExch(&d_flag[row], 1) == 0) {
                int rp = atomicAdd(&d_nrows, 1);
                d_rows[rp] = row;
            }
            const float4* xr = reinterpret_cast<const float4*>(x + (size_t)node * DIM);
            float* y = &d_msg[(size_t)row * DIM];
            #pragma unroll 4
            for (int c4 = 0; c4 < DIM / 4; c4++) {
                float4 xv = __ldg(&xr[c4]);
                asm volatile("red.global.add.v4.f32 [%0], {%1, %2, %3, %4};"
                             :: "l"(y + c4 * 4),
                                "f"(w * xv.x), "f"(w * xv.y), "f"(w * xv.z), "f"(w * xv.w)
                             : "memory");
            }
        }
    }
}

// ---- K9: clear locmap+mask; dynamic rows: gemv + pool + self-clean ------------
__global__ void K9(const float* __restrict__ W1) {
    __shared__ float ys[2 * DIM];
    __shared__ int   sctl[1];
    const int GTH = gridDim.x * blockDim.x;
    const int gtid = blockIdx.x * blockDim.x + threadIdx.x;
    const int t = threadIdx.x;
    for (int i = gtid; i < NH * TOPK; i += GTH) {
        int h = i / TOPK;
        int n = d_sidx[i];
        d_locmap[n * NH + h] = 0;
    }
    for (int i = gtid; i < NMASKW; i += GTH) d_mask[i] = 0u;
    int nr = d_nrows;
    int half = t >> 7, tl = t & 127;
    for (;;) {
        __syncthreads();
        if (t == 0) sctl[0] = atomicAdd(&d_rowctr, 2);
        __syncthreads();
        int rb = sctl[0];
        if (rb >= nr) break;
        int r = rb + half;
        bool active = (r < nr);
        int row = 0;
        if (active) {
            row = d_rows[r];
            ys[half * DIM + tl] = d_msg[(size_t)row * DIM + tl];
            d_msg[(size_t)row * DIM + tl] = 0.0f;   // self-clean
            if (tl == 0) d_flag[row] = 0;           // self-clean
        }
        __syncthreads();
        if (active) {
            const float* yrow = &ys[half * DIM];
            float acc = 0.0f;
            #pragma unroll 8
            for (int c = 0; c < DIM; c++) acc += yrow[c] * __ldg(&W1[c * DIM + tl]);
            if (acc > 0.0f) {
                int g = row / NK, ku = row - g * NK;
                int h = g & 3, jj = g >> 2;
                float pv = d_vals[h * TOPK + jj * NK + ku];
                float sg = 1.0f / (1.0f + __expf(-pv));
                atomicAdd(&d_pooled[jj * DIM + tl], acc * sg);
            }
        }
    }
}

// ---- K10: one block per jj: out row = log_softmax((pooled_jj/4000)@W2) --------
__global__ void K10(const float* __restrict__ W2, float* __restrict__ out) {
    __shared__ float lg[NC];
    __shared__ float mxse[2];
    int jj = blockIdx.x, t = threadIdx.x;
    if (t < NC) {
        float sacc = 0.0f;
        for (int d = 0; d < DIM; d++)
            sacc += d_pooled[jj * DIM + d] * __ldg(&W2[d * NC + t]);
        lg[t] = sacc * (1.0f / 4000.0f);
    }
    __syncthreads();
    d_pooled[jj * DIM + t] = 0.0f;                   // self-clean (t < 128)
    if (jj == 0 && t == 0) { d_nrows = 0; d_rowctr = 0; }
    if (t == 0) {
        float mx = -1e30f;
        for (int c = 0; c < NC; c++) mx = fmaxf(mx, lg[c]);
        float se = 0.0f;
        for (int c = 0; c < NC; c++) se += __expf(lg[c] - mx);
        mxse[0] = mx;
        mxse[1] = __logf(se);
    }
    __syncthreads();
    if (t < NC) out[jj * NC + t] = lg[t] - mxse[0] - mxse[1];
}

// ---------------- host launcher ----------------
extern "C" void kernel_launch(void* const* d_in, const int* in_sizes, int n_in,
                              void* d_out, int out_size) {
    const float* x         = (const float*)d_in[0];
    const float* edge_attr = (const float*)d_in[1];
    const float* w_rank    = (const float*)d_in[2];
    const float* W1        = (const float*)d_in[3];
    const float* W2        = (const float*)d_in[4];
    const int*   ei        = (const int*)d_in[5];
    float*       out       = (float*)d_out;

    const int TB  = 256;
    const int gN  = (N_NODES + TB - 1) / TB;    // 391
    const int gQ  = (NQUAD + TB - 1) / TB;      // 977
    const int gQ2 = (NQHALF + TB - 1) / TB;     // 489

    K1 <<<888, TB>>>(x, w_rank, ei);
    K2a<<<gN, TB>>>();
    K2b<<<gQ2, TB>>>(ei);
    K3 <<<gN, TB>>>();
    K4 <<<NH * NCHUNK, TB>>>();
    K5 <<<NH * NCHUNK, TB>>>();
    K6 <<<gN, TB>>>();
    K7 <<<(NH * CAP) / TB, TB>>>();
    K8 <<<gQ, TB>>>(ei, edge_attr, x);
    K9 <<<888, TB>>>(W1);
    K10<<<NJ, DIM>>>(W2, out);
}